// round 11
// baseline (speedup 1.0000x reference)
#include <cuda_runtime.h>
#include <cuda_bf16.h>
#include <stdint.h>

// B=1024, K=4, E=16, H=2048, I=2048 (fp32 in/out)
#define NE   16
#define HD   2048
#define ID   2048
#define I2D  4096
#define NP   4096
#define BM   128
#define BN   128
#define KT   32              // k elements per smem stage
#define NIT  64              // 2048 / 32

// chunk-transposed smem layout: addr(r,c) = (r>>3)*512 + c*128 + (r&7)*16
// (8 consecutive rows -> 8 distinct 16B lanes; all ldmatrix phases conflict-free)
#define MATB   8192          // 128 rows * 64B
#define SA_H   0
#define SA_L   (1 * MATB)
#define SB_H   (2 * MATB)
#define SB_L   (3 * MATB)
#define STAGEB (4 * MATB)            // 32768
#define NSTAGE 3
#define PS_OFF (NSTAGE * STAGEB)     // 98304
#define AR_OFF (PS_OFF + 512)
#define SMEM_TOTAL (AR_OFF + 512)    // 99328

__device__ int d_cnt[NE];
__device__ int d_bucket[NE][NP];
// pre-split bf16 hi/lo operands
__device__ __nv_bfloat16 d_w1h[(size_t)NE * I2D * HD];
__device__ __nv_bfloat16 d_w1l[(size_t)NE * I2D * HD];
__device__ __nv_bfloat16 d_w2h[(size_t)NE * HD * ID];
__device__ __nv_bfloat16 d_w2l[(size_t)NE * HD * ID];
__device__ __nv_bfloat16 d_th[(size_t)1024 * HD];
__device__ __nv_bfloat16 d_tl[(size_t)1024 * HD];
__device__ __nv_bfloat16 d_gh[(size_t)NP * ID];
__device__ __nv_bfloat16 d_gl[(size_t)NP * ID];

// ---------------- helpers ----------------
__device__ __forceinline__ uint32_t smem_u32(const void* p) {
    uint32_t a;
    asm("{ .reg .u64 t; cvta.to.shared.u64 t, %1; cvt.u32.u64 %0, t; }" : "=r"(a) : "l"(p));
    return a;
}
__device__ __forceinline__ void ldsm4(uint32_t* r, uint32_t a) {
    asm volatile("ldmatrix.sync.aligned.m8n8.x4.shared.b16 {%0,%1,%2,%3}, [%4];"
                 : "=r"(r[0]), "=r"(r[1]), "=r"(r[2]), "=r"(r[3]) : "r"(a));
}
__device__ __forceinline__ void mma16816(float* c, const uint32_t* a, uint32_t b0, uint32_t b1) {
    asm volatile("mma.sync.aligned.m16n8k16.row.col.f32.bf16.bf16.f32 "
                 "{%0,%1,%2,%3}, {%4,%5,%6,%7}, {%8,%9}, {%0,%1,%2,%3};"
                 : "+f"(c[0]), "+f"(c[1]), "+f"(c[2]), "+f"(c[3])
                 : "r"(a[0]), "r"(a[1]), "r"(a[2]), "r"(a[3]), "r"(b0), "r"(b1));
}
__device__ __forceinline__ void cp16(uint32_t dst, const void* src, uint32_t sz) {
    asm volatile("cp.async.cg.shared.global [%0], [%1], 16, %2;"
                 :: "r"(dst), "l"(src), "r"(sz) : "memory");
}
__device__ __forceinline__ void cp_commit() {
    asm volatile("cp.async.commit_group;" ::: "memory");
}
__device__ __forceinline__ void cp_wait1() {
    asm volatile("cp.async.wait_group 1;" ::: "memory");
}
__device__ __forceinline__ void split4(float4 v, uint2& h, uint2& l) {
    __nv_bfloat162 h01 = __floats2bfloat162_rn(v.x, v.y);
    __nv_bfloat162 h23 = __floats2bfloat162_rn(v.z, v.w);
    float2 f01 = __bfloat1622float2(h01);
    float2 f23 = __bfloat1622float2(h23);
    __nv_bfloat162 l01 = __floats2bfloat162_rn(v.x - f01.x, v.y - f01.y);
    __nv_bfloat162 l23 = __floats2bfloat162_rn(v.z - f23.x, v.w - f23.y);
    h.x = *(uint32_t*)&h01; h.y = *(uint32_t*)&h23;
    l.x = *(uint32_t*)&l01; l.y = *(uint32_t*)&l23;
}
__device__ __forceinline__ float swiglu_pair(float xg, float xl) {
    xg = fminf(xg, 7.0f);
    xl = fminf(fmaxf(xl, -7.0f), 7.0f);
    float s = 1.0f / (1.0f + __expf(-1.702f * xg));
    return xg * s * (xl + 1.0f);
}

__global__ void zero_cnt_kernel() {
    if (threadIdx.x < NE) d_cnt[threadIdx.x] = 0;
}
__global__ void scatter_kernel(const int* __restrict__ idx) {
    int p = blockIdx.x * blockDim.x + threadIdx.x;
    if (p < NP) {
        int e = idx[p];
        int pos = atomicAdd(&d_cnt[e], 1);
        d_bucket[e][pos] = p;
    }
}

// ---------------- prepass: fp32 -> bf16 hi/lo splits ----------------
__global__ void cvt_w1_kernel(const float4* __restrict__ src) {
    size_t i = (size_t)blockIdx.x * 256 + threadIdx.x;
    float4 v = __ldg(src + i);
    uint2 h, l; split4(v, h, l);
    ((uint2*)d_w1h)[i] = h; ((uint2*)d_w1l)[i] = l;
}
__global__ void cvt_w2_kernel(const float4* __restrict__ src) {
    size_t i = (size_t)blockIdx.x * 256 + threadIdx.x;
    float4 v = __ldg(src + i);
    uint2 h, l; split4(v, h, l);
    ((uint2*)d_w2h)[i] = h; ((uint2*)d_w2l)[i] = l;
}
__global__ void cvt_t_kernel(const float4* __restrict__ src) {
    size_t i = (size_t)blockIdx.x * 256 + threadIdx.x;
    float4 v = __ldg(src + i);
    uint2 h, l; split4(v, h, l);
    ((uint2*)d_th)[i] = h; ((uint2*)d_tl)[i] = l;
}

// ---------------- compute core ----------------
// aoff = wm*4096 + lane part; boff = wn*2048 + lane part (see offsets below)
__device__ __forceinline__ void compute_stage(uint32_t sbase, uint32_t aoff, uint32_t boff,
                                              float acc[16][4]) {
#pragma unroll
    for (int kc = 0; kc < 2; ++kc) {
        uint32_t Ah[4][4], Al[4][4], Bh[2][4], Bl[2][4];
#pragma unroll
        for (int mt = 0; mt < 4; ++mt) {
            ldsm4(Ah[mt], sbase + SA_H + aoff + mt * 1024 + kc * 256);
            ldsm4(Al[mt], sbase + SA_L + aoff + mt * 1024 + kc * 256);
        }
#pragma unroll
        for (int nt2 = 0; nt2 < 2; ++nt2) {
            ldsm4(Bh[nt2], sbase + SB_H + boff + nt2 * 1024 + kc * 256);
            ldsm4(Bl[nt2], sbase + SB_L + boff + nt2 * 1024 + kc * 256);
        }
#pragma unroll
        for (int mt = 0; mt < 4; ++mt)
#pragma unroll
            for (int nt = 0; nt < 4; ++nt)
                mma16816(acc[mt * 4 + nt], Ah[mt],
                         Bh[nt >> 1][(nt & 1) * 2], Bh[nt >> 1][(nt & 1) * 2 + 1]);
#pragma unroll
        for (int mt = 0; mt < 4; ++mt)
#pragma unroll
            for (int nt = 0; nt < 4; ++nt)
                mma16816(acc[mt * 4 + nt], Ah[mt],
                         Bl[nt >> 1][(nt & 1) * 2], Bl[nt >> 1][(nt & 1) * 2 + 1]);
#pragma unroll
        for (int mt = 0; mt < 4; ++mt)
#pragma unroll
            for (int nt = 0; nt < 4; ++nt)
                mma16816(acc[mt * 4 + nt], Al[mt],
                         Bh[nt >> 1][(nt & 1) * 2], Bh[nt >> 1][(nt & 1) * 2 + 1]);
    }
}
// A fragment: row = wm*64 + mt*16 + (lane&15), chunk c = kc*2 + (lane>>4)
//   addr = SA + (wm*64+mt*16)*64 + kc*256 + [((lane>>3)&1)<<9 | (lane>>4)<<7 | (lane&7)<<4]
__device__ __forceinline__ uint32_t a_lane_off(int lane) {
    return (uint32_t)((((lane >> 3) & 1) << 9) | ((lane >> 4) << 7) | ((lane & 7) << 4));
}
// B fragment: row = wn*32 + nt2*16 + (lane&7) + ((lane>>4)<<3), c = kc*2 + ((lane>>3)&1)
__device__ __forceinline__ uint32_t b_lane_off(int lane) {
    return (uint32_t)((((lane >> 4) & 1) << 9) | (((lane >> 3) & 1) << 7) | ((lane & 7) << 4));
}

// ---------------- cp.async mainloop: 3-stage ring, 1 barrier/iter ----------
__device__ __forceinline__ void mma_mainloop(
    uint32_t su,
    const __nv_bfloat16* __restrict__ aH, const __nv_bfloat16* __restrict__ aL,
    const __nv_bfloat16* __restrict__ bH, const __nv_bfloat16* __restrict__ bL,
    const int* __restrict__ ar, int tid, uint32_t aoff, uint32_t boff,
    float acc[16][4])
{
    const int r0 = tid >> 2, q = tid & 3;
    // chunk-transposed dst: (r>>3)*512 + c*128 + (r&7)*16 ; second chunk +64 rows = +4096
    const uint32_t d0 = (uint32_t)(((tid >> 5) << 9) | (q << 7) | (((tid >> 2) & 7) << 4));
    const int s0 = ar[r0], s1 = ar[r0 + 64];
    const uint32_t szA0 = (s0 >= 0) ? 16u : 0u;
    const uint32_t szA1 = (s1 >= 0) ? 16u : 0u;
    const char* a0h = (const char*)(aH + (size_t)(s0 < 0 ? 0 : s0) * HD + q * 8);
    const char* a0l = (const char*)(aL + (size_t)(s0 < 0 ? 0 : s0) * HD + q * 8);
    const char* a1h = (const char*)(aH + (size_t)(s1 < 0 ? 0 : s1) * HD + q * 8);
    const char* a1l = (const char*)(aL + (size_t)(s1 < 0 ? 0 : s1) * HD + q * 8);
    const char* b0h = (const char*)(bH + (size_t)r0 * HD + q * 8);
    const char* b0l = (const char*)(bL + (size_t)r0 * HD + q * 8);
    const int BSTEP = 64 * HD * 2;   // +64 B-rows in bytes

#pragma unroll
    for (int s = 0; s < 2; ++s) {    // prologue: stages 0,1
        uint32_t sb = su + s * STAGEB;
        int ko = s * 64;             // KT bf16 = 64 bytes per stage
        cp16(sb + SA_H + d0,        a0h + ko, szA0);
        cp16(sb + SA_H + d0 + 4096, a1h + ko, szA1);
        cp16(sb + SA_L + d0,        a0l + ko, szA0);
        cp16(sb + SA_L + d0 + 4096, a1l + ko, szA1);
        cp16(sb + SB_H + d0,        b0h + ko, 16);
        cp16(sb + SB_H + d0 + 4096, b0h + ko + BSTEP, 16);
        cp16(sb + SB_L + d0,        b0l + ko, 16);
        cp16(sb + SB_L + d0 + 4096, b0l + ko + BSTEP, 16);
        cp_commit();
    }

    for (int it = 0; it < NIT; ++it) {
        cp_wait1();                  // stage it's group landed (this thread)
        __syncthreads();             // everyone's copies visible + prev compute done
        if (it + 2 < NIT) {          // prefetch into free buffer (it+2)%3
            uint32_t sb = su + ((it + 2) % 3) * STAGEB;
            int ko = (it + 2) * 64;
            cp16(sb + SA_H + d0,        a0h + ko, szA0);
            cp16(sb + SA_H + d0 + 4096, a1h + ko, szA1);
            cp16(sb + SA_L + d0,        a0l + ko, szA0);
            cp16(sb + SA_L + d0 + 4096, a1l + ko, szA1);
            cp16(sb + SB_H + d0,        b0h + ko, 16);
            cp16(sb + SB_H + d0 + 4096, b0h + ko + BSTEP, 16);
            cp16(sb + SB_L + d0,        b0l + ko, 16);
            cp16(sb + SB_L + d0 + 4096, b0l + ko + BSTEP, 16);
        }
        cp_commit();                 // exactly one group per stage (may be empty)
        compute_stage(su + (it % 3) * STAGEB, aoff, boff, acc);
    }
}

// ---------------- gate_up: g = swiglu(T_gather x W1^T + b1) -> d_gh/d_gl ----
__global__ __launch_bounds__(256, 2) void gate_kernel(const float* __restrict__ b1) {
    const int e = blockIdx.z;
    const int M = d_cnt[e];
    const int m0 = blockIdx.x * BM;
    if (m0 >= M) return;
    const int n0 = blockIdx.y * BN;

    extern __shared__ char smem[];
    uint32_t su = smem_u32(smem);
    const int tid = threadIdx.x, lane = tid & 31, wid = tid >> 5;
    int* ps = (int*)(smem + PS_OFF);
    int* ar = (int*)(smem + AR_OFF);
    if (tid < BM) {
        int r = m0 + tid;
        int p = (r < M) ? d_bucket[e][r] : -1;
        ps[tid] = p;
        ar[tid] = (p >= 0) ? (p >> 2) : -1;
    }
    __syncthreads();

    const int wm = wid >> 2, wn = wid & 3;
    const uint32_t aoff = wm * 4096 + a_lane_off(lane);
    const uint32_t boff = wn * 2048 + b_lane_off(lane);

    float acc[16][4];
#pragma unroll
    for (int i = 0; i < 16; i++) { acc[i][0] = acc[i][1] = acc[i][2] = acc[i][3] = 0.f; }

    mma_mainloop(su, d_th, d_tl,
                 d_w1h + ((size_t)e * I2D + n0) * HD,
                 d_w1l + ((size_t)e * I2D + n0) * HD,
                 ar, tid, aoff, boff, acc);

    // epilogue: bias + swiglu -> bf16 hi/lo activations
    const int g = lane >> 2, q = lane & 3;
    const float* bb = b1 + (size_t)e * I2D;
#pragma unroll
    for (int nt = 0; nt < 4; ++nt) {
        int n = n0 + wn * 32 + nt * 8 + q * 2;
        float bn0 = __ldg(bb + n), bn1 = __ldg(bb + n + 1);
#pragma unroll
        for (int mt = 0; mt < 4; ++mt) {
            float* c = acc[mt * 4 + nt];
            int r0 = wm * 64 + mt * 16 + g;
            if (m0 + r0 < M) {
                int p = ps[r0];
                float gg = swiglu_pair(c[0] + bn0, c[1] + bn1);
                __nv_bfloat16 h = __float2bfloat16(gg);
                __nv_bfloat16 lo = __float2bfloat16(gg - __bfloat162float(h));
                size_t o = (size_t)p * ID + (n >> 1);
                d_gh[o] = h; d_gl[o] = lo;
            }
            int r1 = r0 + 8;
            if (m0 + r1 < M) {
                int p = ps[r1];
                float gg = swiglu_pair(c[2] + bn0, c[3] + bn1);
                __nv_bfloat16 h = __float2bfloat16(gg);
                __nv_bfloat16 lo = __float2bfloat16(gg - __bfloat162float(h));
                size_t o = (size_t)p * ID + (n >> 1);
                d_gh[o] = h; d_gl[o] = lo;
            }
        }
    }
}

// ---------------- down: out = G x W2^T + b2 ----------------
__global__ __launch_bounds__(256, 2) void down_kernel(const float* __restrict__ b2,
                                                      float* __restrict__ out) {
    const int e = blockIdx.z;
    const int M = d_cnt[e];
    const int m0 = blockIdx.x * BM;
    if (m0 >= M) return;
    const int n0 = blockIdx.y * BN;

    extern __shared__ char smem[];
    uint32_t su = smem_u32(smem);
    const int tid = threadIdx.x, lane = tid & 31, wid = tid >> 5;
    int* ps = (int*)(smem + PS_OFF);
    int* ar = (int*)(smem + AR_OFF);
    if (tid < BM) {
        int r = m0 + tid;
        int p = (r < M) ? d_bucket[e][r] : -1;
        ps[tid] = p;
        ar[tid] = p;
    }
    __syncthreads();

    const int wm = wid >> 2, wn = wid & 3;
    const uint32_t aoff = wm * 4096 + a_lane_off(lane);
    const uint32_t boff = wn * 2048 + b_lane_off(lane);

    float acc[16][4];
#pragma unroll
    for (int i = 0; i < 16; i++) { acc[i][0] = acc[i][1] = acc[i][2] = acc[i][3] = 0.f; }

    mma_mainloop(su, d_gh, d_gl,
                 d_w2h + ((size_t)e * HD + n0) * ID,
                 d_w2l + ((size_t)e * HD + n0) * ID,
                 ar, tid, aoff, boff, acc);

    // epilogue: bias, fp32 out
    const int g = lane >> 2, q = lane & 3;
    const float* bb = b2 + (size_t)e * HD;
#pragma unroll
    for (int nt = 0; nt < 4; ++nt) {
        int n = n0 + wn * 32 + nt * 8 + q * 2;
        float bn0 = __ldg(bb + n), bn1 = __ldg(bb + n + 1);
#pragma unroll
        for (int mt = 0; mt < 4; ++mt) {
            float* c = acc[mt * 4 + nt];
            int r0 = wm * 64 + mt * 16 + g;
            if (m0 + r0 < M) {
                int p = ps[r0];
                float2 v = make_float2(c[0] + bn0, c[1] + bn1);
                *(float2*)(out + (size_t)p * HD + n) = v;
            }
            int r1 = r0 + 8;
            if (m0 + r1 < M) {
                int p = ps[r1];
                float2 v = make_float2(c[2] + bn0, c[3] + bn1);
                *(float2*)(out + (size_t)p * HD + n) = v;
            }
        }
    }
}

// ---------------- launch ----------------
extern "C" void kernel_launch(void* const* d_in, const int* in_sizes, int n_in,
                              void* d_out, int out_size) {
    const float* t   = (const float*)d_in[0];
    const int*   idx = (const int*)d_in[1];
    const float* w1  = (const float*)d_in[2];
    const float* b1  = (const float*)d_in[3];
    const float* w2  = (const float*)d_in[4];
    const float* b2  = (const float*)d_in[5];
    float* out = (float*)d_out;

    static cudaStream_t s2 = nullptr;
    static cudaEvent_t evFork = nullptr, evJoin = nullptr;
    if (s2 == nullptr) {
        cudaStreamCreateWithFlags(&s2, cudaStreamNonBlocking);
        cudaEventCreateWithFlags(&evFork, cudaEventDisableTiming);
        cudaEventCreateWithFlags(&evJoin, cudaEventDisableTiming);
        cudaFuncSetAttribute(gate_kernel, cudaFuncAttributeMaxDynamicSharedMemorySize, SMEM_TOTAL);
        cudaFuncSetAttribute(down_kernel, cudaFuncAttributeMaxDynamicSharedMemorySize, SMEM_TOTAL);
    }

    zero_cnt_kernel<<<1, 32>>>();

    // fork: cvt_w2 runs concurrently with cvt_w1 + gate (only down needs w2)
    cudaEventRecord(evFork, 0);
    cudaStreamWaitEvent(s2, evFork, 0);
    cvt_w2_kernel<<<((size_t)NE * HD * ID / 4) / 256, 256, 0, s2>>>((const float4*)w2);
    cudaEventRecord(evJoin, s2);

    scatter_kernel<<<NP / 256, 256>>>(idx);
    cvt_t_kernel<<<(1024 * HD / 4) / 256, 256>>>((const float4*)t);
    cvt_w1_kernel<<<((size_t)NE * I2D * HD / 4) / 256, 256>>>((const float4*)w1);

    gate_kernel<<<dim3(NP / BM, I2D / BN, NE), 256, SMEM_TOTAL>>>(b1);

    cudaStreamWaitEvent(0, evJoin, 0);   // join before down consumes w2 splits
    down_kernel<<<dim3(NP / BM, HD / BN, NE), 256, SMEM_TOTAL>>>(b2, out);
}

// round 12
// speedup vs baseline: 1.1726x; 1.1726x over previous
#include <cuda_runtime.h>
#include <cuda_bf16.h>
#include <stdint.h>

// B=1024, K=4, E=16, H=2048, I=2048 (fp32 in/out)
#define NE   16
#define HD   2048
#define ID   2048
#define I2D  4096
#define NP   4096
#define BM   128
#define BN   128
#define KT   32            // k elements per smem stage
#define NIT  64            // 2048 / 32
#define SROW 80            // smem row stride bytes (32 bf16 = 64B data + 16B pad)
#define MATB (128 * SROW)  // 10240 B per matrix tile
#define SA_H 0
#define SA_L (1 * MATB)
#define SB_H (2 * MATB)
#define SB_L (3 * MATB)
#define STAGEB (4 * MATB)          // 40960
#define PS_OFF (2 * STAGEB)        // 81920
#define AR_OFF (PS_OFF + 512)
#define SMEM_TOTAL (AR_OFF + 512)  // 82944

#define W1_SLICES 32

__device__ int d_cnt[NE];
__device__ int d_ready[NE];        // w1 conversion release flags
__device__ int d_bucket[NE][NP];
// pre-split bf16 hi/lo operands
__device__ __nv_bfloat16 d_w1h[(size_t)NE * I2D * HD];
__device__ __nv_bfloat16 d_w1l[(size_t)NE * I2D * HD];
__device__ __nv_bfloat16 d_w2h[(size_t)NE * HD * ID];
__device__ __nv_bfloat16 d_w2l[(size_t)NE * HD * ID];
__device__ __nv_bfloat16 d_th[(size_t)1024 * HD];
__device__ __nv_bfloat16 d_tl[(size_t)1024 * HD];
__device__ __nv_bfloat16 d_gh[(size_t)NP * ID];
__device__ __nv_bfloat16 d_gl[(size_t)NP * ID];

// ---------------- helpers ----------------
__device__ __forceinline__ uint32_t smem_u32(const void* p) {
    uint32_t a;
    asm("{ .reg .u64 t; cvta.to.shared.u64 t, %1; cvt.u32.u64 %0, t; }" : "=r"(a) : "l"(p));
    return a;
}
__device__ __forceinline__ void ldsm4(uint32_t* r, uint32_t a) {
    asm volatile("ldmatrix.sync.aligned.m8n8.x4.shared.b16 {%0,%1,%2,%3}, [%4];"
                 : "=r"(r[0]), "=r"(r[1]), "=r"(r[2]), "=r"(r[3]) : "r"(a));
}
__device__ __forceinline__ void mma16816(float* c, const uint32_t* a, uint32_t b0, uint32_t b1) {
    asm volatile("mma.sync.aligned.m16n8k16.row.col.f32.bf16.bf16.f32 "
                 "{%0,%1,%2,%3}, {%4,%5,%6,%7}, {%8,%9}, {%0,%1,%2,%3};"
                 : "+f"(c[0]), "+f"(c[1]), "+f"(c[2]), "+f"(c[3])
                 : "r"(a[0]), "r"(a[1]), "r"(a[2]), "r"(a[3]), "r"(b0), "r"(b1));
}
__device__ __forceinline__ void cp16(uint32_t dst, const void* src, uint32_t sz) {
    asm volatile("cp.async.cg.shared.global [%0], [%1], 16, %2;"
                 :: "r"(dst), "l"(src), "r"(sz) : "memory");
}
__device__ __forceinline__ void cp_commit() {
    asm volatile("cp.async.commit_group;" ::: "memory");
}
__device__ __forceinline__ void cp_wait1() {
    asm volatile("cp.async.wait_group 1;" ::: "memory");
}
__device__ __forceinline__ void split4(float4 v, uint2& h, uint2& l) {
    __nv_bfloat162 h01 = __floats2bfloat162_rn(v.x, v.y);
    __nv_bfloat162 h23 = __floats2bfloat162_rn(v.z, v.w);
    float2 f01 = __bfloat1622float2(h01);
    float2 f23 = __bfloat1622float2(h23);
    __nv_bfloat162 l01 = __floats2bfloat162_rn(v.x - f01.x, v.y - f01.y);
    __nv_bfloat162 l23 = __floats2bfloat162_rn(v.z - f23.x, v.w - f23.y);
    h.x = *(uint32_t*)&h01; h.y = *(uint32_t*)&h23;
    l.x = *(uint32_t*)&l01; l.y = *(uint32_t*)&l23;
}
__device__ __forceinline__ float swiglu_pair(float xg, float xl) {
    xg = fminf(xg, 7.0f);
    xl = fminf(fmaxf(xl, -7.0f), 7.0f);
    float s = 1.0f / (1.0f + __expf(-1.702f * xg));
    return xg * s * (xl + 1.0f);
}

__global__ void zero_cnt_kernel() {
    if (threadIdx.x < NE) { d_cnt[threadIdx.x] = 0; d_ready[threadIdx.x] = 0; }
}
__global__ void scatter_kernel(const int* __restrict__ idx) {
    int p = blockIdx.x * blockDim.x + threadIdx.x;
    if (p < NP) {
        int e = idx[p];
        int pos = atomicAdd(&d_cnt[e], 1);
        d_bucket[e][pos] = p;
    }
}
__global__ void cvt_t_kernel(const float4* __restrict__ src) {
    size_t i = (size_t)blockIdx.x * 256 + threadIdx.x;
    float4 v = __ldg(src + i);
    uint2 h, l; split4(v, h, l);
    ((uint2*)d_th)[i] = h; ((uint2*)d_tl)[i] = l;
}

// ---------------- compute core (R8/R10 verified layout) ----------------
__device__ __forceinline__ void compute_stage(uint32_t sbase, uint32_t aoff, uint32_t boff,
                                              float acc[16][4]) {
#pragma unroll
    for (int kc = 0; kc < 2; ++kc) {
        uint32_t Ah[4][4], Al[4][4], Bh[2][4], Bl[2][4];
#pragma unroll
        for (int mt = 0; mt < 4; ++mt) {
            ldsm4(Ah[mt], sbase + SA_H + aoff + mt * 1280 + kc * 32);
            ldsm4(Al[mt], sbase + SA_L + aoff + mt * 1280 + kc * 32);
        }
#pragma unroll
        for (int nt2 = 0; nt2 < 2; ++nt2) {
            ldsm4(Bh[nt2], sbase + SB_H + boff + nt2 * 1280 + kc * 32);
            ldsm4(Bl[nt2], sbase + SB_L + boff + nt2 * 1280 + kc * 32);
        }
#pragma unroll
        for (int mt = 0; mt < 4; ++mt)
#pragma unroll
            for (int nt = 0; nt < 4; ++nt)
                mma16816(acc[mt * 4 + nt], Ah[mt],
                         Bh[nt >> 1][(nt & 1) * 2], Bh[nt >> 1][(nt & 1) * 2 + 1]);
#pragma unroll
        for (int mt = 0; mt < 4; ++mt)
#pragma unroll
            for (int nt = 0; nt < 4; ++nt)
                mma16816(acc[mt * 4 + nt], Ah[mt],
                         Bl[nt >> 1][(nt & 1) * 2], Bl[nt >> 1][(nt & 1) * 2 + 1]);
#pragma unroll
        for (int mt = 0; mt < 4; ++mt)
#pragma unroll
            for (int nt = 0; nt < 4; ++nt)
                mma16816(acc[mt * 4 + nt], Al[mt],
                         Bh[nt >> 1][(nt & 1) * 2], Bh[nt >> 1][(nt & 1) * 2 + 1]);
    }
}
__device__ __forceinline__ uint32_t a_ldsm_off(int wm, int lane) {
    return (uint32_t)(wm * 64 + (lane & 15)) * SROW + ((lane >> 4) * 16);
}
__device__ __forceinline__ uint32_t b_ldsm_off(int wn, int lane) {
    return (uint32_t)(wn * 32 + (lane & 7) + ((lane & 16) >> 1)) * SROW + ((lane & 8) * 2);
}

// ---------------- cp.async mainloop (exact R10 structure) ----------------
__device__ __forceinline__ void mma_mainloop(
    uint32_t su,
    const __nv_bfloat16* __restrict__ aH, const __nv_bfloat16* __restrict__ aL,
    const __nv_bfloat16* __restrict__ bH, const __nv_bfloat16* __restrict__ bL,
    const int* __restrict__ ar, int tid, uint32_t aoff, uint32_t boff,
    float acc[16][4])
{
    const int r0 = tid >> 2, q = tid & 3;
    const uint32_t d0 = (uint32_t)r0 * SROW + q * 16;   // chunk 2: +64 rows -> +5120
    const int s0 = ar[r0], s1 = ar[r0 + 64];
    const uint32_t szA0 = (s0 >= 0) ? 16u : 0u;
    const uint32_t szA1 = (s1 >= 0) ? 16u : 0u;
    const char* a0h = (const char*)(aH + (size_t)(s0 < 0 ? 0 : s0) * HD + q * 8);
    const char* a0l = (const char*)(aL + (size_t)(s0 < 0 ? 0 : s0) * HD + q * 8);
    const char* a1h = (const char*)(aH + (size_t)(s1 < 0 ? 0 : s1) * HD + q * 8);
    const char* a1l = (const char*)(aL + (size_t)(s1 < 0 ? 0 : s1) * HD + q * 8);
    const char* b0h = (const char*)(bH + (size_t)r0 * HD + q * 8);
    const char* b0l = (const char*)(bL + (size_t)r0 * HD + q * 8);
    const int BSTEP = 64 * HD * 2;

#pragma unroll
    for (int s = 0; s < 2; ++s) {
        uint32_t sb = su + s * STAGEB;
        int ko = s * 64;
        cp16(sb + SA_H + d0,        a0h + ko, szA0);
        cp16(sb + SA_H + d0 + 5120, a1h + ko, szA1);
        cp16(sb + SA_L + d0,        a0l + ko, szA0);
        cp16(sb + SA_L + d0 + 5120, a1l + ko, szA1);
        cp16(sb + SB_H + d0,        b0h + ko, 16);
        cp16(sb + SB_H + d0 + 5120, b0h + ko + BSTEP, 16);
        cp16(sb + SB_L + d0,        b0l + ko, 16);
        cp16(sb + SB_L + d0 + 5120, b0l + ko + BSTEP, 16);
        cp_commit();
    }

    for (int it = 0; it < NIT; ++it) {
        cp_wait1();
        __syncthreads();
        compute_stage(su + (it & 1) * STAGEB, aoff, boff, acc);
        __syncthreads();
        if (it + 2 < NIT) {
            uint32_t sb = su + (it & 1) * STAGEB;
            int ko = (it + 2) * 64;
            cp16(sb + SA_H + d0,        a0h + ko, szA0);
            cp16(sb + SA_H + d0 + 5120, a1h + ko, szA1);
            cp16(sb + SA_L + d0,        a0l + ko, szA0);
            cp16(sb + SA_L + d0 + 5120, a1l + ko, szA1);
            cp16(sb + SB_H + d0,        b0h + ko, 16);
            cp16(sb + SB_H + d0 + 5120, b0h + ko + BSTEP, 16);
            cp16(sb + SB_L + d0,        b0l + ko, 16);
            cp16(sb + SB_L + d0 + 5120, b0l + ko + BSTEP, 16);
        }
        cp_commit();
    }
}

// ---------------- gate_up (+ merged w1/w2 conversion planes) ----------------
// grid (32, 34, 16): y=0 -> cvt w1 slices, y=1 -> cvt w2 slices, y>=2 -> gate tile
__global__ __launch_bounds__(256, 2) void gate_kernel(
    const float4* __restrict__ w1f, const float4* __restrict__ w2f,
    const float* __restrict__ b1) {
    const int e = blockIdx.z;
    const int tid = threadIdx.x;

    if (blockIdx.y == 0) {   // convert w1[e] slice: 65536 float4 per block
        size_t off = (size_t)e * (I2D * HD / 4) + (size_t)blockIdx.x * 65536 + tid;
#pragma unroll 4
        for (int i = 0; i < 256; ++i) {
            size_t idx = off + (size_t)i * 256;
            float4 v = __ldg(w1f + idx);
            uint2 h, l; split4(v, h, l);
            ((uint2*)d_w1h)[idx] = h; ((uint2*)d_w1l)[idx] = l;
        }
        __threadfence();
        __syncthreads();
        if (tid == 0) atomicAdd(&d_ready[e], 1);
        return;
    }
    if (blockIdx.y == 1) {   // convert w2[e] slice: 32768 float4 per block
        size_t off = (size_t)e * (HD * ID / 4) + (size_t)blockIdx.x * 32768 + tid;
#pragma unroll 4
        for (int i = 0; i < 128; ++i) {
            size_t idx = off + (size_t)i * 256;
            float4 v = __ldg(w2f + idx);
            uint2 h, l; split4(v, h, l);
            ((uint2*)d_w2h)[idx] = h; ((uint2*)d_w2l)[idx] = l;
        }
        return;              // down launches after gate completes; no flag needed
    }

    const int M = d_cnt[e];
    const int m0 = blockIdx.x * BM;
    if (m0 >= M) return;
    const int n0 = (blockIdx.y - 2) * BN;

    extern __shared__ char smem[];
    uint32_t su = smem_u32(smem);
    const int lane = tid & 31, wid = tid >> 5;
    int* ps = (int*)(smem + PS_OFF);
    int* ar = (int*)(smem + AR_OFF);
    if (tid < BM) {
        int r = m0 + tid;
        int p = (r < M) ? d_bucket[e][r] : -1;
        ps[tid] = p;
        ar[tid] = (p >= 0) ? (p >> 2) : -1;
    }
    // wait for this expert's w1 conversion (cvt blocks precede us in dispatch order)
    if (tid == 0) {
        while (atomicAdd(&d_ready[e], 0) < W1_SLICES) {}
    }
    __syncthreads();

    const int wm = wid >> 2, wn = wid & 3;
    const uint32_t aoff = a_ldsm_off(wm, lane);
    const uint32_t boff = b_ldsm_off(wn, lane);

    float acc[16][4];
#pragma unroll
    for (int i = 0; i < 16; i++) { acc[i][0] = acc[i][1] = acc[i][2] = acc[i][3] = 0.f; }

    mma_mainloop(su, d_th, d_tl,
                 d_w1h + ((size_t)e * I2D + n0) * HD,
                 d_w1l + ((size_t)e * I2D + n0) * HD,
                 ar, tid, aoff, boff, acc);

    // epilogue: bias + swiglu -> bf16 hi/lo activations
    const int g = lane >> 2, q = lane & 3;
    const float* bb = b1 + (size_t)e * I2D;
#pragma unroll
    for (int nt = 0; nt < 4; ++nt) {
        int n = n0 + wn * 32 + nt * 8 + q * 2;
        float bn0 = __ldg(bb + n), bn1 = __ldg(bb + n + 1);
#pragma unroll
        for (int mt = 0; mt < 4; ++mt) {
            float* c = acc[mt * 4 + nt];
            int r0 = wm * 64 + mt * 16 + g;
            if (m0 + r0 < M) {
                int p = ps[r0];
                float gg = swiglu_pair(c[0] + bn0, c[1] + bn1);
                __nv_bfloat16 h = __float2bfloat16(gg);
                __nv_bfloat16 lo = __float2bfloat16(gg - __bfloat162float(h));
                size_t o = (size_t)p * ID + (n >> 1);
                d_gh[o] = h; d_gl[o] = lo;
            }
            int r1 = r0 + 8;
            if (m0 + r1 < M) {
                int p = ps[r1];
                float gg = swiglu_pair(c[2] + bn0, c[3] + bn1);
                __nv_bfloat16 h = __float2bfloat16(gg);
                __nv_bfloat16 lo = __float2bfloat16(gg - __bfloat162float(h));
                size_t o = (size_t)p * ID + (n >> 1);
                d_gh[o] = h; d_gl[o] = lo;
            }
        }
    }
}

// ---------------- down: out = G x W2^T + b2 ----------------
__global__ __launch_bounds__(256, 2) void down_kernel(const float* __restrict__ b2,
                                                      float* __restrict__ out) {
    const int e = blockIdx.z;
    const int M = d_cnt[e];
    const int m0 = blockIdx.x * BM;
    if (m0 >= M) return;
    const int n0 = blockIdx.y * BN;

    extern __shared__ char smem[];
    uint32_t su = smem_u32(smem);
    const int tid = threadIdx.x, lane = tid & 31, wid = tid >> 5;
    int* ps = (int*)(smem + PS_OFF);
    int* ar = (int*)(smem + AR_OFF);
    if (tid < BM) {
        int r = m0 + tid;
        int p = (r < M) ? d_bucket[e][r] : -1;
        ps[tid] = p;
        ar[tid] = p;
    }
    __syncthreads();

    const int wm = wid >> 2, wn = wid & 3;
    const uint32_t aoff = a_ldsm_off(wm, lane);
    const uint32_t boff = b_ldsm_off(wn, lane);

    float acc[16][4];
#pragma unroll
    for (int i = 0; i < 16; i++) { acc[i][0] = acc[i][1] = acc[i][2] = acc[i][3] = 0.f; }

    mma_mainloop(su, d_gh, d_gl,
                 d_w2h + ((size_t)e * HD + n0) * ID,
                 d_w2l + ((size_t)e * HD + n0) * ID,
                 ar, tid, aoff, boff, acc);

    // epilogue: bias, fp32 out
    const int g = lane >> 2, q = lane & 3;
    const float* bb = b2 + (size_t)e * HD;
#pragma unroll
    for (int nt = 0; nt < 4; ++nt) {
        int n = n0 + wn * 32 + nt * 8 + q * 2;
        float bn0 = __ldg(bb + n), bn1 = __ldg(bb + n + 1);
#pragma unroll
        for (int mt = 0; mt < 4; ++mt) {
            float* c = acc[mt * 4 + nt];
            int r0 = wm * 64 + mt * 16 + g;
            if (m0 + r0 < M) {
                int p = ps[r0];
                float2 v = make_float2(c[0] + bn0, c[1] + bn1);
                *(float2*)(out + (size_t)p * HD + n) = v;
            }
            int r1 = r0 + 8;
            if (m0 + r1 < M) {
                int p = ps[r1];
                float2 v = make_float2(c[2] + bn0, c[3] + bn1);
                *(float2*)(out + (size_t)p * HD + n) = v;
            }
        }
    }
}

// ---------------- launch ----------------
extern "C" void kernel_launch(void* const* d_in, const int* in_sizes, int n_in,
                              void* d_out, int out_size) {
    const float* t   = (const float*)d_in[0];
    const int*   idx = (const int*)d_in[1];
    const float* w1  = (const float*)d_in[2];
    const float* b1  = (const float*)d_in[3];
    const float* w2  = (const float*)d_in[4];
    const float* b2  = (const float*)d_in[5];
    float* out = (float*)d_out;

    cudaFuncSetAttribute(gate_kernel, cudaFuncAttributeMaxDynamicSharedMemorySize, SMEM_TOTAL);
    cudaFuncSetAttribute(down_kernel, cudaFuncAttributeMaxDynamicSharedMemorySize, SMEM_TOTAL);

    zero_cnt_kernel<<<1, 32>>>();
    scatter_kernel<<<NP / 256, 256>>>(idx);
    cvt_t_kernel<<<(1024 * HD / 4) / 256, 256>>>((const float4*)t);

    // gate grid: y=0 cvt-w1, y=1 cvt-w2, y in [2,34) gate n-tiles
    gate_kernel<<<dim3(NP / BM, 2 + I2D / BN, NE), 256, SMEM_TOTAL>>>(
        (const float4*)w1, (const float4*)w2, b1);
    down_kernel<<<dim3(NP / BM, HD / BN, NE), 256, SMEM_TOTAL>>>(b2, out);
}

// round 13
// speedup vs baseline: 1.3646x; 1.1637x over previous
#include <cuda_runtime.h>
#include <cuda_bf16.h>
#include <stdint.h>

// B=1024, K=4, E=16, H=2048, I=2048 (fp32 in/out)
#define NE   16
#define HD   2048
#define ID   2048
#define I2D  4096
#define NP   4096
#define BM   128
#define BN   128
#define KT   32            // k elements per smem stage
#define NIT  64            // 2048 / 32
#define SROW 80            // smem row stride bytes (32 bf16 = 64B data + 16B pad)
#define MATB (128 * SROW)  // 10240 B per matrix tile
#define SA_H 0
#define SA_L (1 * MATB)
#define SB_H (2 * MATB)
#define SB_L (3 * MATB)
#define STAGEB (4 * MATB)            // 40960
#define NSTG 3
#define PS_OFF (NSTG * STAGEB)       // 122880
#define AR_OFF (PS_OFF + 512)
#define SMEM_TOTAL (AR_OFF + 512)    // 123904

__device__ int d_cnt[NE];
__device__ int d_bucket[NE][NP];
__device__ __nv_bfloat16 d_gh[(size_t)NP * ID];
__device__ __nv_bfloat16 d_gl[(size_t)NP * ID];

// ---------------- helpers ----------------
__device__ __forceinline__ uint32_t smem_u32(const void* p) {
    uint32_t a;
    asm("{ .reg .u64 t; cvta.to.shared.u64 t, %1; cvt.u32.u64 %0, t; }" : "=r"(a) : "l"(p));
    return a;
}
__device__ __forceinline__ void ldsm4(uint32_t* r, uint32_t a) {
    asm volatile("ldmatrix.sync.aligned.m8n8.x4.shared.b16 {%0,%1,%2,%3}, [%4];"
                 : "=r"(r[0]), "=r"(r[1]), "=r"(r[2]), "=r"(r[3]) : "r"(a));
}
__device__ __forceinline__ void mma16816(float* c, const uint32_t* a, uint32_t b0, uint32_t b1) {
    asm volatile("mma.sync.aligned.m16n8k16.row.col.f32.bf16.bf16.f32 "
                 "{%0,%1,%2,%3}, {%4,%5,%6,%7}, {%8,%9}, {%0,%1,%2,%3};"
                 : "+f"(c[0]), "+f"(c[1]), "+f"(c[2]), "+f"(c[3])
                 : "r"(a[0]), "r"(a[1]), "r"(a[2]), "r"(a[3]), "r"(b0), "r"(b1));
}
__device__ __forceinline__ void split4(float4 v, uint2& h, uint2& l) {
    __nv_bfloat162 h01 = __floats2bfloat162_rn(v.x, v.y);
    __nv_bfloat162 h23 = __floats2bfloat162_rn(v.z, v.w);
    float2 f01 = __bfloat1622float2(h01);
    float2 f23 = __bfloat1622float2(h23);
    __nv_bfloat162 l01 = __floats2bfloat162_rn(v.x - f01.x, v.y - f01.y);
    __nv_bfloat162 l23 = __floats2bfloat162_rn(v.z - f23.x, v.w - f23.y);
    h.x = *(uint32_t*)&h01; h.y = *(uint32_t*)&h23;
    l.x = *(uint32_t*)&l01; l.y = *(uint32_t*)&l23;
}
__device__ __forceinline__ float swiglu_pair(float xg, float xl) {
    xg = fminf(xg, 7.0f);
    xl = fminf(fmaxf(xl, -7.0f), 7.0f);
    float s = 1.0f / (1.0f + __expf(-1.702f * xg));
    return xg * s * (xl + 1.0f);
}

__global__ void zero_cnt_kernel() {
    if (threadIdx.x < NE) d_cnt[threadIdx.x] = 0;
}
__global__ void scatter_kernel(const int* __restrict__ idx) {
    int p = blockIdx.x * blockDim.x + threadIdx.x;
    if (p < NP) {
        int e = idx[p];
        int pos = atomicAdd(&d_cnt[e], 1);
        d_bucket[e][pos] = p;
    }
}

// ---------------- fragment load + MMA term group (verified R8 layout) -------
__device__ __forceinline__ void ldsm_frags(uint32_t sbase, uint32_t aoff, uint32_t boff, int kc,
                                           uint32_t Ah[4][4], uint32_t Al[4][4],
                                           uint32_t Bh[2][4], uint32_t Bl[2][4]) {
#pragma unroll
    for (int mt = 0; mt < 4; ++mt) {
        ldsm4(Ah[mt], sbase + SA_H + aoff + mt * 1280 + kc * 32);
        ldsm4(Al[mt], sbase + SA_L + aoff + mt * 1280 + kc * 32);
    }
#pragma unroll
    for (int n2 = 0; n2 < 2; ++n2) {
        ldsm4(Bh[n2], sbase + SB_H + boff + n2 * 1280 + kc * 32);
        ldsm4(Bl[n2], sbase + SB_L + boff + n2 * 1280 + kc * 32);
    }
}
__device__ __forceinline__ void mma_term(float acc[16][4],
                                         const uint32_t A[4][4], const uint32_t B[2][4]) {
#pragma unroll
    for (int mt = 0; mt < 4; ++mt)
#pragma unroll
        for (int nt = 0; nt < 4; ++nt)
            mma16816(acc[mt * 4 + nt], A[mt],
                     B[nt >> 1][(nt & 1) * 2], B[nt >> 1][(nt & 1) * 2 + 1]);
}
__device__ __forceinline__ uint32_t a_ldsm_off(int wm, int lane) {
    return (uint32_t)(wm * 64 + (lane & 15)) * SROW + ((lane >> 4) * 16);
}
__device__ __forceinline__ uint32_t b_ldsm_off(int wn, int lane) {
    return (uint32_t)(wn * 32 + (lane & 7) + ((lane & 16) >> 1)) * SROW + ((lane & 8) * 2);
}

// ---------------- gate_up: g = swiglu(T_gather x W1^T + b1) -> d_gh/d_gl ----
__global__ __launch_bounds__(256, 1) void gate_kernel(
    const float* __restrict__ t, const float* __restrict__ w1,
    const float* __restrict__ b1) {
    const int e = blockIdx.z;
    const int M = d_cnt[e];
    const int m0 = blockIdx.x * BM;
    if (m0 >= M) return;
    const int n0 = blockIdx.y * BN;

    extern __shared__ char smem[];
    uint32_t su = smem_u32(smem);
    const int tid = threadIdx.x, lane = tid & 31, wid = tid >> 5;
    int* ps = (int*)(smem + PS_OFF);
    int* ar = (int*)(smem + AR_OFF);
    if (tid < BM) {
        int r = m0 + tid;
        int p = (r < M) ? d_bucket[e][r] : -1;
        ps[tid] = p;
        ar[tid] = (p >= 0) ? (p >> 2) : -1;
    }
    __syncthreads();

    // loader: 4 chunks per matrix per thread (128 rows x 32 fp32)
    uint32_t soff[4];
    const float* aP[4];
    const float* bP[4];
    bool avv[4];
    const float* wb = w1 + ((size_t)e * I2D + n0) * HD;
#pragma unroll
    for (int i = 0; i < 4; i++) {
        int c = tid + i * 256;
        int row = c >> 3, c8 = c & 7;
        soff[i] = (uint32_t)row * SROW + c8 * 8;
        int tok = ar[row];
        avv[i] = (tok >= 0);
        aP[i] = t + (size_t)(tok < 0 ? 0 : tok) * HD + c8 * 4;
        bP[i] = wb + (size_t)row * HD + c8 * 4;
    }

    const int wm = wid >> 2, wn = wid & 3;
    const uint32_t aoff = a_ldsm_off(wm, lane);
    const uint32_t boff = b_ldsm_off(wn, lane);

    float acc[16][4];
#pragma unroll
    for (int i = 0; i < 16; i++) { acc[i][0] = acc[i][1] = acc[i][2] = acc[i][3] = 0.f; }

    const float4 fz = make_float4(0.f, 0.f, 0.f, 0.f);
    float4 va[4], vb[4];

#define GATE_LDG(k0_) do { const int _k0 = (k0_);                              \
    _Pragma("unroll") for (int i = 0; i < 4; i++) {                            \
        va[i] = avv[i] ? *(const float4*)(aP[i] + _k0) : fz;                   \
        vb[i] = *(const float4*)(bP[i] + _k0);                                 \
    } } while (0)
#define GATE_STS_A(stb_) do { char* _st = (stb_);                              \
    _Pragma("unroll") for (int i = 0; i < 4; i++) { uint2 h, l;                \
        split4(va[i], h, l);                                                   \
        *(uint2*)(_st + SA_H + soff[i]) = h;                                   \
        *(uint2*)(_st + SA_L + soff[i]) = l; } } while (0)
#define GATE_STS_B(stb_) do { char* _st = (stb_);                              \
    _Pragma("unroll") for (int i = 0; i < 4; i++) { uint2 h, l;                \
        split4(vb[i], h, l);                                                   \
        *(uint2*)(_st + SB_H + soff[i]) = h;                                   \
        *(uint2*)(_st + SB_L + soff[i]) = l; } } while (0)

    // prologue: fill stages 0,1; preload chunk 2 into regs
    GATE_LDG(0);      GATE_STS_A(smem);          GATE_STS_B(smem);
    GATE_LDG(KT);     GATE_STS_A(smem + STAGEB); GATE_STS_B(smem + STAGEB);
    GATE_LDG(2 * KT);

    for (int it = 0; it < NIT; ++it) {
        __syncthreads();                       // stage it%3 visible; stage (it+2)%3 free
        const uint32_t sb = su + (it % 3) * STAGEB;
        char* stw = smem + ((it + 2) % 3) * STAGEB;
        const bool doSts = (it + 2) < NIT;
        const bool doLdg = (it + 3) < NIT;
        uint32_t Ah[4][4], Al[4][4], Bh[2][4], Bl[2][4];
        ldsm_frags(sb, aoff, boff, 0, Ah, Al, Bh, Bl);
        mma_term(acc, Ah, Bh);
        if (doSts) GATE_STS_A(stw);            // hide STS under tensor work
        mma_term(acc, Ah, Bl);
        if (doSts) GATE_STS_B(stw);
        mma_term(acc, Al, Bh);
        ldsm_frags(sb, aoff, boff, 1, Ah, Al, Bh, Bl);
        mma_term(acc, Ah, Bh);
        if (doLdg) GATE_LDG((it + 3) * KT);    // hide LDG issue; lands during next iter
        mma_term(acc, Ah, Bl);
        mma_term(acc, Al, Bh);
    }

    // epilogue: bias + swiglu -> bf16 hi/lo activations
    const int g = lane >> 2, q = lane & 3;
    const float* bb = b1 + (size_t)e * I2D;
#pragma unroll
    for (int nt = 0; nt < 4; ++nt) {
        int n = n0 + wn * 32 + nt * 8 + q * 2;
        float bn0 = __ldg(bb + n), bn1 = __ldg(bb + n + 1);
#pragma unroll
        for (int mt = 0; mt < 4; ++mt) {
            float* c = acc[mt * 4 + nt];
            int r0 = wm * 64 + mt * 16 + g;
            if (m0 + r0 < M) {
                int p = ps[r0];
                float gg = swiglu_pair(c[0] + bn0, c[1] + bn1);
                __nv_bfloat16 h = __float2bfloat16(gg);
                __nv_bfloat16 lo = __float2bfloat16(gg - __bfloat162float(h));
                size_t o = (size_t)p * ID + (n >> 1);
                d_gh[o] = h; d_gl[o] = lo;
            }
            int r1 = r0 + 8;
            if (m0 + r1 < M) {
                int p = ps[r1];
                float gg = swiglu_pair(c[2] + bn0, c[3] + bn1);
                __nv_bfloat16 h = __float2bfloat16(gg);
                __nv_bfloat16 lo = __float2bfloat16(gg - __bfloat162float(h));
                size_t o = (size_t)p * ID + (n >> 1);
                d_gh[o] = h; d_gl[o] = lo;
            }
        }
    }
}

// ---------------- down: out = G x W2^T + b2 ----------------
__global__ __launch_bounds__(256, 1) void down_kernel(
    const float* __restrict__ w2, const float* __restrict__ b2,
    float* __restrict__ out) {
    const int e = blockIdx.z;
    const int M = d_cnt[e];
    const int m0 = blockIdx.x * BM;
    if (m0 >= M) return;
    const int n0 = blockIdx.y * BN;

    extern __shared__ char smem[];
    uint32_t su = smem_u32(smem);
    const int tid = threadIdx.x, lane = tid & 31, wid = tid >> 5;
    int* ps = (int*)(smem + PS_OFF);
    if (tid < BM) {
        int r = m0 + tid;
        ps[tid] = (r < M) ? d_bucket[e][r] : -1;
    }
    __syncthreads();

    // A loader: bf16 hi/lo from gate (2 x 16B chunks per thread per matrix)
    uint32_t soffA[2];
    const uint4* ghP[2];
    const uint4* glP[2];
    bool avA[2];
#pragma unroll
    for (int i = 0; i < 2; i++) {
        int c = tid + i * 256;
        int row = c >> 2, c4 = c & 3;
        soffA[i] = (uint32_t)row * SROW + c4 * 16;
        int p = ps[row];
        avA[i] = (p >= 0);
        size_t off = (size_t)(p < 0 ? 0 : p) * ID + c4 * 8;
        ghP[i] = (const uint4*)(d_gh + off);
        glP[i] = (const uint4*)(d_gl + off);
    }
    // B loader: fp32 w2 with in-loop split
    uint32_t soffB[4];
    const float* bP[4];
    const float* wb = w2 + ((size_t)e * HD + n0) * ID;
#pragma unroll
    for (int i = 0; i < 4; i++) {
        int c = tid + i * 256;
        int row = c >> 3, c8 = c & 7;
        soffB[i] = (uint32_t)row * SROW + c8 * 8;
        bP[i] = wb + (size_t)row * ID + c8 * 4;
    }

    const int wm = wid >> 2, wn = wid & 3;
    const uint32_t aoff = a_ldsm_off(wm, lane);
    const uint32_t boff = b_ldsm_off(wn, lane);

    float acc[16][4];
#pragma unroll
    for (int i = 0; i < 16; i++) { acc[i][0] = acc[i][1] = acc[i][2] = acc[i][3] = 0.f; }

    const uint4 uz = make_uint4(0, 0, 0, 0);
    uint4 vah[2], val[2];
    float4 vb[4];

#define DOWN_LDG(k0_) do { const int _k0 = (k0_);                              \
    _Pragma("unroll") for (int i = 0; i < 2; i++) {                            \
        vah[i] = avA[i] ? __ldg((const uint4*)((const __nv_bfloat16*)ghP[i] + _k0)) : uz; \
        val[i] = avA[i] ? __ldg((const uint4*)((const __nv_bfloat16*)glP[i] + _k0)) : uz; \
    }                                                                          \
    _Pragma("unroll") for (int i = 0; i < 4; i++)                              \
        vb[i] = *(const float4*)(bP[i] + _k0); } while (0)
#define DOWN_STS_A(stb_) do { char* _st = (stb_);                              \
    _Pragma("unroll") for (int i = 0; i < 2; i++) {                            \
        *(uint4*)(_st + SA_H + soffA[i]) = vah[i];                             \
        *(uint4*)(_st + SA_L + soffA[i]) = val[i]; } } while (0)
#define DOWN_STS_B(stb_) do { char* _st = (stb_);                              \
    _Pragma("unroll") for (int i = 0; i < 4; i++) { uint2 h, l;                \
        split4(vb[i], h, l);                                                   \
        *(uint2*)(_st + SB_H + soffB[i]) = h;                                  \
        *(uint2*)(_st + SB_L + soffB[i]) = l; } } while (0)

    DOWN_LDG(0);      DOWN_STS_A(smem);          DOWN_STS_B(smem);
    DOWN_LDG(KT);     DOWN_STS_A(smem + STAGEB); DOWN_STS_B(smem + STAGEB);
    DOWN_LDG(2 * KT);

    for (int it = 0; it < NIT; ++it) {
        __syncthreads();
        const uint32_t sb = su + (it % 3) * STAGEB;
        char* stw = smem + ((it + 2) % 3) * STAGEB;
        const bool doSts = (it + 2) < NIT;
        const bool doLdg = (it + 3) < NIT;
        uint32_t Ah[4][4], Al[4][4], Bh[2][4], Bl[2][4];
        ldsm_frags(sb, aoff, boff, 0, Ah, Al, Bh, Bl);
        mma_term(acc, Ah, Bh);
        if (doSts) DOWN_STS_A(stw);
        mma_term(acc, Ah, Bl);
        if (doSts) DOWN_STS_B(stw);
        mma_term(acc, Al, Bh);
        ldsm_frags(sb, aoff, boff, 1, Ah, Al, Bh, Bl);
        mma_term(acc, Ah, Bh);
        if (doLdg) DOWN_LDG((it + 3) * KT);
        mma_term(acc, Ah, Bl);
        mma_term(acc, Al, Bh);
    }

    // epilogue: bias, fp32 out
    const int g = lane >> 2, q = lane & 3;
    const float* bb = b2 + (size_t)e * HD;
#pragma unroll
    for (int nt = 0; nt < 4; ++nt) {
        int n = n0 + wn * 32 + nt * 8 + q * 2;
        float bn0 = __ldg(bb + n), bn1 = __ldg(bb + n + 1);
#pragma unroll
        for (int mt = 0; mt < 4; ++mt) {
            float* c = acc[mt * 4 + nt];
            int r0 = wm * 64 + mt * 16 + g;
            if (m0 + r0 < M) {
                int p = ps[r0];
                float2 v = make_float2(c[0] + bn0, c[1] + bn1);
                *(float2*)(out + (size_t)p * HD + n) = v;
            }
            int r1 = r0 + 8;
            if (m0 + r1 < M) {
                int p = ps[r1];
                float2 v = make_float2(c[2] + bn0, c[3] + bn1);
                *(float2*)(out + (size_t)p * HD + n) = v;
            }
        }
    }
}

// ---------------- launch ----------------
extern "C" void kernel_launch(void* const* d_in, const int* in_sizes, int n_in,
                              void* d_out, int out_size) {
    const float* t   = (const float*)d_in[0];
    const int*   idx = (const int*)d_in[1];
    const float* w1  = (const float*)d_in[2];
    const float* b1  = (const float*)d_in[3];
    const float* w2  = (const float*)d_in[4];
    const float* b2  = (const float*)d_in[5];
    float* out = (float*)d_out;

    cudaFuncSetAttribute(gate_kernel, cudaFuncAttributeMaxDynamicSharedMemorySize, SMEM_TOTAL);
    cudaFuncSetAttribute(down_kernel, cudaFuncAttributeMaxDynamicSharedMemorySize, SMEM_TOTAL);

    zero_cnt_kernel<<<1, 32>>>();
    scatter_kernel<<<NP / 256, 256>>>(idx);
    gate_kernel<<<dim3(NP / BM, I2D / BN, NE), 256, SMEM_TOTAL>>>(t, w1, b1);
    down_kernel<<<dim3(NP / BM, HD / BN, NE), 256, SMEM_TOTAL>>>(w2, b2, out);
}

// round 14
// speedup vs baseline: 1.4732x; 1.0796x over previous
#include <cuda_runtime.h>
#include <cuda_bf16.h>
#include <stdint.h>

// B=1024, K=4, E=16, H=2048, I=2048 (fp32 in/out)
#define NE   16
#define HD   2048
#define ID   2048
#define I2D  4096
#define NP   4096
#define BM   128
#define BN   128
#define KT   32            // k elements per smem stage
#define NIT  64            // 2048 / 32
#define SROW 80            // smem row stride bytes (32 bf16 = 64B data + 16B pad)
#define MATB (128 * SROW)  // 10240 B per matrix tile
#define SA_H 0
#define SA_L (1 * MATB)
#define SB_H (2 * MATB)
#define SB_L (3 * MATB)
#define STAGEB (4 * MATB)            // 40960
#define NSTG 3
#define PS_OFF (NSTG * STAGEB)       // 122880
#define AR_OFF (PS_OFF + 512)
#define SMEM_TOTAL (AR_OFF + 512)    // 123904

__device__ int d_cnt[NE];
__device__ int d_bucket[NE][NP];
__device__ __nv_bfloat16 d_gh[(size_t)NP * ID];
__device__ __nv_bfloat16 d_gl[(size_t)NP * ID];

// ---------------- helpers ----------------
__device__ __forceinline__ uint32_t smem_u32(const void* p) {
    uint32_t a;
    asm("{ .reg .u64 t; cvta.to.shared.u64 t, %1; cvt.u32.u64 %0, t; }" : "=r"(a) : "l"(p));
    return a;
}
__device__ __forceinline__ void ldsm4(uint32_t* r, uint32_t a) {
    asm volatile("ldmatrix.sync.aligned.m8n8.x4.shared.b16 {%0,%1,%2,%3}, [%4];"
                 : "=r"(r[0]), "=r"(r[1]), "=r"(r[2]), "=r"(r[3]) : "r"(a));
}
__device__ __forceinline__ void mma16816(float* c, const uint32_t* a, uint32_t b0, uint32_t b1) {
    asm volatile("mma.sync.aligned.m16n8k16.row.col.f32.bf16.bf16.f32 "
                 "{%0,%1,%2,%3}, {%4,%5,%6,%7}, {%8,%9}, {%0,%1,%2,%3};"
                 : "+f"(c[0]), "+f"(c[1]), "+f"(c[2]), "+f"(c[3])
                 : "r"(a[0]), "r"(a[1]), "r"(a[2]), "r"(a[3]), "r"(b0), "r"(b1));
}
__device__ __forceinline__ void split4(float4 v, uint2& h, uint2& l) {
    __nv_bfloat162 h01 = __floats2bfloat162_rn(v.x, v.y);
    __nv_bfloat162 h23 = __floats2bfloat162_rn(v.z, v.w);
    float2 f01 = __bfloat1622float2(h01);
    float2 f23 = __bfloat1622float2(h23);
    __nv_bfloat162 l01 = __floats2bfloat162_rn(v.x - f01.x, v.y - f01.y);
    __nv_bfloat162 l23 = __floats2bfloat162_rn(v.z - f23.x, v.w - f23.y);
    h.x = *(uint32_t*)&h01; h.y = *(uint32_t*)&h23;
    l.x = *(uint32_t*)&l01; l.y = *(uint32_t*)&l23;
}
__device__ __forceinline__ float swiglu_pair(float xg, float xl) {
    xg = fminf(xg, 7.0f);
    xl = fminf(fmaxf(xl, -7.0f), 7.0f);
    float s = 1.0f / (1.0f + __expf(-1.702f * xg));
    return xg * s * (xl + 1.0f);
}

__global__ void zero_cnt_kernel() {
    if (threadIdx.x < NE) d_cnt[threadIdx.x] = 0;
}
__global__ void scatter_kernel(const int* __restrict__ idx) {
    int p = blockIdx.x * blockDim.x + threadIdx.x;
    if (p < NP) {
        int e = idx[p];
        int pos = atomicAdd(&d_cnt[e], 1);
        d_bucket[e][pos] = p;
    }
}

// ---------------- fragment loads (verified R8 layout), hi/lo separated ------
__device__ __forceinline__ void ldsm_hi(uint32_t sbase, uint32_t aoff, uint32_t boff, int kc,
                                        uint32_t Ah[4][4], uint32_t Bh[2][4]) {
#pragma unroll
    for (int mt = 0; mt < 4; ++mt)
        ldsm4(Ah[mt], sbase + SA_H + aoff + mt * 1280 + kc * 32);
#pragma unroll
    for (int n2 = 0; n2 < 2; ++n2)
        ldsm4(Bh[n2], sbase + SB_H + boff + n2 * 1280 + kc * 32);
}
__device__ __forceinline__ void ldsm_lo(uint32_t sbase, uint32_t aoff, uint32_t boff, int kc,
                                        uint32_t Al[4][4], uint32_t Bl[2][4]) {
#pragma unroll
    for (int mt = 0; mt < 4; ++mt)
        ldsm4(Al[mt], sbase + SA_L + aoff + mt * 1280 + kc * 32);
#pragma unroll
    for (int n2 = 0; n2 < 2; ++n2)
        ldsm4(Bl[n2], sbase + SB_L + boff + n2 * 1280 + kc * 32);
}
__device__ __forceinline__ void mma_term(float acc[16][4],
                                         const uint32_t A[4][4], const uint32_t B[2][4]) {
#pragma unroll
    for (int mt = 0; mt < 4; ++mt)
#pragma unroll
        for (int nt = 0; nt < 4; ++nt)
            mma16816(acc[mt * 4 + nt], A[mt],
                     B[nt >> 1][(nt & 1) * 2], B[nt >> 1][(nt & 1) * 2 + 1]);
}
__device__ __forceinline__ uint32_t a_ldsm_off(int wm, int lane) {
    return (uint32_t)(wm * 64 + (lane & 15)) * SROW + ((lane >> 4) * 16);
}
__device__ __forceinline__ uint32_t b_ldsm_off(int wn, int lane) {
    return (uint32_t)(wn * 32 + (lane & 7) + ((lane & 16) >> 1)) * SROW + ((lane & 8) * 2);
}

// ---------------- gate_up: g = swiglu(T_gather x W1^T + b1) -> d_gh/d_gl ----
__global__ __launch_bounds__(256, 1) void gate_kernel(
    const float* __restrict__ t, const float* __restrict__ w1,
    const float* __restrict__ b1) {
    const int e = blockIdx.z;
    const int M = d_cnt[e];
    const int m0 = blockIdx.x * BM;
    if (m0 >= M) return;
    const int n0 = blockIdx.y * BN;

    extern __shared__ char smem[];
    uint32_t su = smem_u32(smem);
    const int tid = threadIdx.x, lane = tid & 31, wid = tid >> 5;
    int* ps = (int*)(smem + PS_OFF);
    int* ar = (int*)(smem + AR_OFF);
    if (tid < BM) {
        int r = m0 + tid;
        int p = (r < M) ? d_bucket[e][r] : -1;
        ps[tid] = p;
        ar[tid] = (p >= 0) ? (p >> 2) : -1;
    }
    __syncthreads();

    uint32_t soff[4];
    const float* aP[4];
    const float* bP[4];
    bool avv[4];
    const float* wb = w1 + ((size_t)e * I2D + n0) * HD;
#pragma unroll
    for (int i = 0; i < 4; i++) {
        int c = tid + i * 256;
        int row = c >> 3, c8 = c & 7;
        soff[i] = (uint32_t)row * SROW + c8 * 8;
        int tok = ar[row];
        avv[i] = (tok >= 0);
        aP[i] = t + (size_t)(tok < 0 ? 0 : tok) * HD + c8 * 4;
        bP[i] = wb + (size_t)row * HD + c8 * 4;
    }

    const int wm = wid >> 2, wn = wid & 3;
    const uint32_t aoff = a_ldsm_off(wm, lane);
    const uint32_t boff = b_ldsm_off(wn, lane);

    float acc[16][4];
#pragma unroll
    for (int i = 0; i < 16; i++) { acc[i][0] = acc[i][1] = acc[i][2] = acc[i][3] = 0.f; }

    const float4 fz = make_float4(0.f, 0.f, 0.f, 0.f);
    float4 va[4], vb[4];

#define GATE_LDG(k0_) do { const int _k0 = (k0_);                              \
    _Pragma("unroll") for (int i = 0; i < 4; i++) {                            \
        va[i] = avv[i] ? *(const float4*)(aP[i] + _k0) : fz;                   \
        vb[i] = *(const float4*)(bP[i] + _k0);                                 \
    } } while (0)
#define GATE_STS_A(stb_) do { char* _st = (stb_);                              \
    _Pragma("unroll") for (int i = 0; i < 4; i++) { uint2 h, l;                \
        split4(va[i], h, l);                                                   \
        *(uint2*)(_st + SA_H + soff[i]) = h;                                   \
        *(uint2*)(_st + SA_L + soff[i]) = l; } } while (0)
#define GATE_STS_B(stb_) do { char* _st = (stb_);                              \
    _Pragma("unroll") for (int i = 0; i < 4; i++) { uint2 h, l;                \
        split4(vb[i], h, l);                                                   \
        *(uint2*)(_st + SB_H + soff[i]) = h;                                   \
        *(uint2*)(_st + SB_L + soff[i]) = l; } } while (0)

    // prologue: fill stages 0,1; preload chunk 2; prefetch stage0 kc0 hi frags
    GATE_LDG(0);      GATE_STS_A(smem);          GATE_STS_B(smem);
    GATE_LDG(KT);     GATE_STS_A(smem + STAGEB); GATE_STS_B(smem + STAGEB);
    GATE_LDG(2 * KT);
    __syncthreads();
    uint32_t AhP[4][4], BhP[2][4];
    ldsm_hi(su, aoff, boff, 0, AhP, BhP);

    for (int it = 0; it < NIT; ++it) {
        __syncthreads();                      // stage it%3 visible; (it+2)%3 free
        const uint32_t sb  = su + (it % 3) * STAGEB;
        const uint32_t sbn = su + ((it + 1) % 3) * STAGEB;
        char* stw = smem + ((it + 2) % 3) * STAGEB;
        const bool doSts = (it + 2) < NIT;
        const bool doLdg = (it + 3) < NIT;
        const bool doPre = (it + 1) < NIT;
        // kc0: hi frags already in regs -> term1 issues with no LDSM wait
        uint32_t Al0[4][4], Bl0[2][4];
        ldsm_lo(sb, aoff, boff, 0, Al0, Bl0);
        mma_term(acc, AhP, BhP);
        if (doSts) GATE_STS_A(stw);
        mma_term(acc, AhP, Bl0);
        if (doSts) GATE_STS_B(stw);
        mma_term(acc, Al0, BhP);
        // kc1: dependency-first ordering (hi before lo)
        uint32_t Ah1[4][4], Bh1[2][4], Al1[4][4], Bl1[2][4];
        ldsm_hi(sb, aoff, boff, 1, Ah1, Bh1);
        ldsm_lo(sb, aoff, boff, 1, Al1, Bl1);
        mma_term(acc, Ah1, Bh1);
        if (doLdg) GATE_LDG((it + 3) * KT);
        mma_term(acc, Ah1, Bl1);
        // prefetch next iter's kc0 hi frags from stage (it+1)%3 (valid now)
        if (doPre) ldsm_hi(sbn, aoff, boff, 0, AhP, BhP);
        mma_term(acc, Al1, Bh1);
    }

    // epilogue: bias + swiglu -> bf16 hi/lo activations
    const int g = lane >> 2, q = lane & 3;
    const float* bb = b1 + (size_t)e * I2D;
#pragma unroll
    for (int nt = 0; nt < 4; ++nt) {
        int n = n0 + wn * 32 + nt * 8 + q * 2;
        float bn0 = __ldg(bb + n), bn1 = __ldg(bb + n + 1);
#pragma unroll
        for (int mt = 0; mt < 4; ++mt) {
            float* c = acc[mt * 4 + nt];
            int r0 = wm * 64 + mt * 16 + g;
            if (m0 + r0 < M) {
                int p = ps[r0];
                float gg = swiglu_pair(c[0] + bn0, c[1] + bn1);
                __nv_bfloat16 h = __float2bfloat16(gg);
                __nv_bfloat16 lo = __float2bfloat16(gg - __bfloat162float(h));
                size_t o = (size_t)p * ID + (n >> 1);
                d_gh[o] = h; d_gl[o] = lo;
            }
            int r1 = r0 + 8;
            if (m0 + r1 < M) {
                int p = ps[r1];
                float gg = swiglu_pair(c[2] + bn0, c[3] + bn1);
                __nv_bfloat16 h = __float2bfloat16(gg);
                __nv_bfloat16 lo = __float2bfloat16(gg - __bfloat162float(h));
                size_t o = (size_t)p * ID + (n >> 1);
                d_gh[o] = h; d_gl[o] = lo;
            }
        }
    }
}

// ---------------- down: out = G x W2^T + b2 ----------------
__global__ __launch_bounds__(256, 1) void down_kernel(
    const float* __restrict__ w2, const float* __restrict__ b2,
    float* __restrict__ out) {
    const int e = blockIdx.z;
    const int M = d_cnt[e];
    const int m0 = blockIdx.x * BM;
    if (m0 >= M) return;
    const int n0 = blockIdx.y * BN;

    extern __shared__ char smem[];
    uint32_t su = smem_u32(smem);
    const int tid = threadIdx.x, lane = tid & 31, wid = tid >> 5;
    int* ps = (int*)(smem + PS_OFF);
    if (tid < BM) {
        int r = m0 + tid;
        ps[tid] = (r < M) ? d_bucket[e][r] : -1;
    }
    __syncthreads();

    uint32_t soffA[2];
    const uint4* ghP[2];
    const uint4* glP[2];
    bool avA[2];
#pragma unroll
    for (int i = 0; i < 2; i++) {
        int c = tid + i * 256;
        int row = c >> 2, c4 = c & 3;
        soffA[i] = (uint32_t)row * SROW + c4 * 16;
        int p = ps[row];
        avA[i] = (p >= 0);
        size_t off = (size_t)(p < 0 ? 0 : p) * ID + c4 * 8;
        ghP[i] = (const uint4*)(d_gh + off);
        glP[i] = (const uint4*)(d_gl + off);
    }
    uint32_t soffB[4];
    const float* bP[4];
    const float* wb = w2 + ((size_t)e * HD + n0) * ID;
#pragma unroll
    for (int i = 0; i < 4; i++) {
        int c = tid + i * 256;
        int row = c >> 3, c8 = c & 7;
        soffB[i] = (uint32_t)row * SROW + c8 * 8;
        bP[i] = wb + (size_t)row * ID + c8 * 4;
    }

    const int wm = wid >> 2, wn = wid & 3;
    const uint32_t aoff = a_ldsm_off(wm, lane);
    const uint32_t boff = b_ldsm_off(wn, lane);

    float acc[16][4];
#pragma unroll
    for (int i = 0; i < 16; i++) { acc[i][0] = acc[i][1] = acc[i][2] = acc[i][3] = 0.f; }

    const uint4 uz = make_uint4(0, 0, 0, 0);
    uint4 vah[2], val[2];
    float4 vb[4];

#define DOWN_LDG(k0_) do { const int _k0 = (k0_);                              \
    _Pragma("unroll") for (int i = 0; i < 2; i++) {                            \
        vah[i] = avA[i] ? __ldg((const uint4*)((const __nv_bfloat16*)ghP[i] + _k0)) : uz; \
        val[i] = avA[i] ? __ldg((const uint4*)((const __nv_bfloat16*)glP[i] + _k0)) : uz; \
    }                                                                          \
    _Pragma("unroll") for (int i = 0; i < 4; i++)                              \
        vb[i] = *(const float4*)(bP[i] + _k0); } while (0)
#define DOWN_STS_A(stb_) do { char* _st = (stb_);                              \
    _Pragma("unroll") for (int i = 0; i < 2; i++) {                            \
        *(uint4*)(_st + SA_H + soffA[i]) = vah[i];                             \
        *(uint4*)(_st + SA_L + soffA[i]) = val[i]; } } while (0)
#define DOWN_STS_B(stb_) do { char* _st = (stb_);                              \
    _Pragma("unroll") for (int i = 0; i < 4; i++) { uint2 h, l;                \
        split4(vb[i], h, l);                                                   \
        *(uint2*)(_st + SB_H + soffB[i]) = h;                                  \
        *(uint2*)(_st + SB_L + soffB[i]) = l; } } while (0)

    DOWN_LDG(0);      DOWN_STS_A(smem);          DOWN_STS_B(smem);
    DOWN_LDG(KT);     DOWN_STS_A(smem + STAGEB); DOWN_STS_B(smem + STAGEB);
    DOWN_LDG(2 * KT);
    __syncthreads();
    uint32_t AhP[4][4], BhP[2][4];
    ldsm_hi(su, aoff, boff, 0, AhP, BhP);

    for (int it = 0; it < NIT; ++it) {
        __syncthreads();
        const uint32_t sb  = su + (it % 3) * STAGEB;
        const uint32_t sbn = su + ((it + 1) % 3) * STAGEB;
        char* stw = smem + ((it + 2) % 3) * STAGEB;
        const bool doSts = (it + 2) < NIT;
        const bool doLdg = (it + 3) < NIT;
        const bool doPre = (it + 1) < NIT;
        uint32_t Al0[4][4], Bl0[2][4];
        ldsm_lo(sb, aoff, boff, 0, Al0, Bl0);
        mma_term(acc, AhP, BhP);
        if (doSts) DOWN_STS_A(stw);
        mma_term(acc, AhP, Bl0);
        if (doSts) DOWN_STS_B(stw);
        mma_term(acc, Al0, BhP);
        uint32_t Ah1[4][4], Bh1[2][4], Al1[4][4], Bl1[2][4];
        ldsm_hi(sb, aoff, boff, 1, Ah1, Bh1);
        ldsm_lo(sb, aoff, boff, 1, Al1, Bl1);
        mma_term(acc, Ah1, Bh1);
        if (doLdg) DOWN_LDG((it + 3) * KT);
        mma_term(acc, Ah1, Bl1);
        if (doPre) ldsm_hi(sbn, aoff, boff, 0, AhP, BhP);
        mma_term(acc, Al1, Bh1);
    }

    // epilogue: bias, fp32 out
    const int g = lane >> 2, q = lane & 3;
    const float* bb = b2 + (size_t)e * HD;
#pragma unroll
    for (int nt = 0; nt < 4; ++nt) {
        int n = n0 + wn * 32 + nt * 8 + q * 2;
        float bn0 = __ldg(bb + n), bn1 = __ldg(bb + n + 1);
#pragma unroll
        for (int mt = 0; mt < 4; ++mt) {
            float* c = acc[mt * 4 + nt];
            int r0 = wm * 64 + mt * 16 + g;
            if (m0 + r0 < M) {
                int p = ps[r0];
                float2 v = make_float2(c[0] + bn0, c[1] + bn1);
                *(float2*)(out + (size_t)p * HD + n) = v;
            }
            int r1 = r0 + 8;
            if (m0 + r1 < M) {
                int p = ps[r1];
                float2 v = make_float2(c[2] + bn0, c[3] + bn1);
                *(float2*)(out + (size_t)p * HD + n) = v;
            }
        }
    }
}

// ---------------- launch ----------------
extern "C" void kernel_launch(void* const* d_in, const int* in_sizes, int n_in,
                              void* d_out, int out_size) {
    const float* t   = (const float*)d_in[0];
    const int*   idx = (const int*)d_in[1];
    const float* w1  = (const float*)d_in[2];
    const float* b1  = (const float*)d_in[3];
    const float* w2  = (const float*)d_in[4];
    const float* b2  = (const float*)d_in[5];
    float* out = (float*)d_out;

    cudaFuncSetAttribute(gate_kernel, cudaFuncAttributeMaxDynamicSharedMemorySize, SMEM_TOTAL);
    cudaFuncSetAttribute(down_kernel, cudaFuncAttributeMaxDynamicSharedMemorySize, SMEM_TOTAL);

    zero_cnt_kernel<<<1, 32>>>();
    scatter_kernel<<<NP / 256, 256>>>(idx);
    gate_kernel<<<dim3(NP / BM, I2D / BN, NE), 256, SMEM_TOTAL>>>(t, w1, b1);
    down_kernel<<<dim3(NP / BM, HD / BN, NE), 256, SMEM_TOTAL>>>(w2, b2, out);
}